// round 3
// baseline (speedup 1.0000x reference)
#include <cuda_runtime.h>
#include <cuda_bf16.h>
#include <cstdint>

#define BB   64          // batch
#define DD   12          // tree depth
#define VV   128         // vocab/input dim
#define HH   256         // hidden
#define NOPS 20
#define NN   1280        // 3H (iou) + H (f0) + H (f1)
#define KK   640         // V + 2H
#define RMAX 131072      // BB << (DD-1)

// ---------------- scratch (static device memory; no allocation at runtime) ----
__device__ __nv_bfloat16 g_W[NN * KK];                  // packed weights, [n][k], bf16
__device__ float         g_G[(size_t)RMAX * NN];        // pre-activations scratch
__device__ __nv_bfloat16 g_h[2][(size_t)RMAX * HH];     // ping-pong h (bf16)
__device__ float         g_c[2][(size_t)RMAX * HH];     // ping-pong c (fp32)

// ---------------- weight repack -----------------------------------------------
// Wcat_t[n][k]:
//   k in [0,128)    : x row  -> Wiou (n<768), Wf (768<=n<1024), Wf (1024<=n)
//   k in [128,384)  : h_child0 -> Uiou[0], Uf[0][0], Uf[1][0]
//   k in [384,640)  : h_child1 -> Uiou[1], Uf[0][1], Uf[1][1]
__global__ void prep_kernel(const float* __restrict__ Wiou,
                            const float* __restrict__ Uiou,
                            const float* __restrict__ Wf,
                            const float* __restrict__ Uf)
{
    int idx = blockIdx.x * blockDim.x + threadIdx.x;
    if (idx >= NN * KK) return;
    int n = idx / KK;
    int k = idx % KK;
    float v;
    if (k < VV) {
        if (n < 768)       v = Wiou[k * 768 + n];
        else if (n < 1024) v = Wf[k * HH + (n - 768)];
        else               v = Wf[k * HH + (n - 1024)];
    } else {
        int j  = (k - VV) >> 8;     // which child (0/1)
        int hh = (k - VV) & 255;
        if (n < 768)       v = Uiou[(j * HH + hh) * 768 + n];
        else if (n < 1024) v = Uf[((0 * 2 + j) * HH + hh) * HH + (n - 768)];
        else               v = Uf[((1 * 2 + j) * HH + hh) * HH + (n - 1024)];
    }
    g_W[(size_t)n * KK + k] = __float2bfloat16(v);
}

// ---------------- fused-gather bf16 GEMM --------------------------------------
// G[r, n] = sum_k X[r,k] * Wcat_t[n,k], X gathered on the fly:
//   X[r, 0:128]    = arg_hot[b, (m-1)+node, :]
//   X[r, 128:384]  = h_prev[b*2m + 2*node]      (zeros at leaf level)
//   X[r, 384:640]  = h_prev[b*2m + 2*node + 1]
__global__ __launch_bounds__(256) void gemm_kernel(const float* __restrict__ arg_hot,
                                                   int level, int leaf)
{
    const int m = 1 << level;
    const int R = BB * m;
    const __nv_bfloat16* __restrict__ h_prev = g_h[(level + 1) & 1];

    __shared__ __align__(16) __nv_bfloat16 As[128][40];   // +8 pad: conflict-free
    __shared__ __align__(16) __nv_bfloat16 Bs[128][40];

    const int tid  = threadIdx.x;
    const int M0   = blockIdx.x * 128;
    const int N0   = blockIdx.y * 128;
    const int warp = tid >> 5;
    const int lane = tid & 31;
    const int wm   = warp >> 2;   // 2 warps in M
    const int wn   = warp & 3;    // 4 warps in N

    float acc[4][4][4];
    #pragma unroll
    for (int a = 0; a < 4; ++a)
        #pragma unroll
        for (int c = 0; c < 4; ++c)
            #pragma unroll
            for (int d = 0; d < 4; ++d) acc[a][c][d] = 0.f;

    const int kk = (tid & 7) << 2;   // 4-elem chunk in K
    const int i0 = tid >> 3;         // base row

    for (int K0 = 0; K0 < KK; K0 += 32) {
        // ---- load A tile (gather + fp32->bf16) ----
        #pragma unroll
        for (int it = 0; it < 4; ++it) {
            int i = i0 + it * 32;
            int r = M0 + i;
            float4 v = make_float4(0.f, 0.f, 0.f, 0.f);
            if (r < R) {
                int bb   = r >> level;
                int node = r & (m - 1);
                int kg   = K0 + kk;
                if (kg < VV) {
                    size_t idx = ((size_t)bb * 4095 + (m - 1) + node) * VV + kg;
                    v = *(const float4*)(arg_hot + idx);
                } else if (!leaf) {
                    int j  = (kg - VV) >> 8;
                    int hh = (kg - VV) & 255;
                    size_t child = (size_t)bb * (m << 1) + (node << 1) + j;
                    uint2 uu = *(const uint2*)(h_prev + child * HH + hh);
                    __nv_bfloat162 p0 = *reinterpret_cast<__nv_bfloat162*>(&uu.x);
                    __nv_bfloat162 p1 = *reinterpret_cast<__nv_bfloat162*>(&uu.y);
                    v.x = __bfloat162float(p0.x); v.y = __bfloat162float(p0.y);
                    v.z = __bfloat162float(p1.x); v.w = __bfloat162float(p1.y);
                }
            }
            __nv_bfloat162* dst = (__nv_bfloat162*)&As[i][kk];
            dst[0] = __floats2bfloat162_rn(v.x, v.y);
            dst[1] = __floats2bfloat162_rn(v.z, v.w);
        }
        // ---- load B tile ----
        #pragma unroll
        for (int it = 0; it < 4; ++it) {
            int nrow = i0 + it * 32;
            uint2 w = *(const uint2*)(g_W + (size_t)(N0 + nrow) * KK + K0 + kk);
            *(uint2*)&Bs[nrow][kk] = w;
        }
        __syncthreads();

        // ---- compute: 2 k-steps of m16n8k16 ----
        #pragma unroll
        for (int ks = 0; ks < 32; ks += 16) {
            uint32_t af[4][4];
            #pragma unroll
            for (int mi = 0; mi < 4; ++mi) {
                int row = wm * 64 + mi * 16 + (lane >> 2);
                int col = ks + ((lane & 3) << 1);
                af[mi][0] = *(const uint32_t*)&As[row][col];
                af[mi][1] = *(const uint32_t*)&As[row + 8][col];
                af[mi][2] = *(const uint32_t*)&As[row][col + 8];
                af[mi][3] = *(const uint32_t*)&As[row + 8][col + 8];
            }
            uint32_t bfr[4][2];
            #pragma unroll
            for (int ni = 0; ni < 4; ++ni) {
                int bn = wn * 32 + ni * 8 + (lane >> 2);
                int bk = ks + ((lane & 3) << 1);
                bfr[ni][0] = *(const uint32_t*)&Bs[bn][bk];
                bfr[ni][1] = *(const uint32_t*)&Bs[bn][bk + 8];
            }
            #pragma unroll
            for (int mi = 0; mi < 4; ++mi)
                #pragma unroll
                for (int ni = 0; ni < 4; ++ni) {
                    asm volatile(
                        "mma.sync.aligned.m16n8k16.row.col.f32.bf16.bf16.f32 "
                        "{%0,%1,%2,%3}, {%4,%5,%6,%7}, {%8,%9}, {%0,%1,%2,%3};\n"
                        : "+f"(acc[mi][ni][0]), "+f"(acc[mi][ni][1]),
                          "+f"(acc[mi][ni][2]), "+f"(acc[mi][ni][3])
                        : "r"(af[mi][0]), "r"(af[mi][1]), "r"(af[mi][2]), "r"(af[mi][3]),
                          "r"(bfr[ni][0]), "r"(bfr[ni][1]));
                }
        }
        __syncthreads();
    }

    // ---- store G (sector-aligned 8B stores) ----
    #pragma unroll
    for (int mi = 0; mi < 4; ++mi) {
        int row = M0 + wm * 64 + mi * 16 + (lane >> 2);
        #pragma unroll
        for (int ni = 0; ni < 4; ++ni) {
            int col = N0 + wn * 32 + ni * 8 + ((lane & 3) << 1);
            if (row < R)
                *(float2*)&g_G[(size_t)row * NN + col] =
                    make_float2(acc[mi][ni][0], acc[mi][ni][1]);
            if (row + 8 < R)
                *(float2*)&g_G[(size_t)(row + 8) * NN + col] =
                    make_float2(acc[mi][ni][2], acc[mi][ni][3]);
        }
    }
}

// ---------------- gates ------------------------------------------------------
__device__ __forceinline__ float sigf(float x) {
    return __fdividef(1.0f, 1.0f + __expf(-x));
}
__device__ __forceinline__ float tanhf_fast(float x) {
    return __fdividef(2.0f, 1.0f + __expf(-2.0f * x)) - 1.0f;
}

__global__ void gates_kernel(const float* __restrict__ biou,
                             const float* __restrict__ bfv,
                             int level, int leaf)
{
    const int m = 1 << level;
    const int R = BB * m;
    int idx = blockIdx.x * blockDim.x + threadIdx.x;
    if (idx >= R * (HH / 4)) return;
    int r = idx >> 6;
    int j = (idx & 63) << 2;

    const float* Gr = g_G + (size_t)r * NN;
    float4 gi = *(const float4*)(Gr + j);
    float4 go = *(const float4*)(Gr + 256 + j);
    float4 gu = *(const float4*)(Gr + 512 + j);
    float4 g0 = *(const float4*)(Gr + 768 + j);
    float4 g1 = *(const float4*)(Gr + 1024 + j);
    float4 bi = *(const float4*)(biou + j);
    float4 bo = *(const float4*)(biou + 256 + j);
    float4 bu = *(const float4*)(biou + 512 + j);
    float4 bfb = *(const float4*)(bfv + j);

    float4 c0 = make_float4(0.f, 0.f, 0.f, 0.f), c1 = c0;
    if (!leaf) {
        const float* c_prev = g_c[(level + 1) & 1];
        int bb = r >> level, node = r & (m - 1);
        size_t ch = ((size_t)bb * (m << 1) + (node << 1)) * HH;
        c0 = *(const float4*)(c_prev + ch + j);
        c1 = *(const float4*)(c_prev + ch + HH + j);
    }

    float GI[4] = {gi.x, gi.y, gi.z, gi.w};
    float GO[4] = {go.x, go.y, go.z, go.w};
    float GU[4] = {gu.x, gu.y, gu.z, gu.w};
    float F0[4] = {g0.x, g0.y, g0.z, g0.w};
    float F1[4] = {g1.x, g1.y, g1.z, g1.w};
    float BI[4] = {bi.x, bi.y, bi.z, bi.w};
    float BO[4] = {bo.x, bo.y, bo.z, bo.w};
    float BU[4] = {bu.x, bu.y, bu.z, bu.w};
    float BF[4] = {bfb.x, bfb.y, bfb.z, bfb.w};
    float C0[4] = {c0.x, c0.y, c0.z, c0.w};
    float C1[4] = {c1.x, c1.y, c1.z, c1.w};

    float cv[4], hv[4];
    #pragma unroll
    for (int t = 0; t < 4; ++t) {
        float iv = sigf(GI[t] + BI[t]);
        float ov = sigf(GO[t] + BO[t]);
        float uv = tanhf_fast(GU[t] + BU[t]);
        float f0 = sigf(F0[t] + BF[t]);
        float f1 = sigf(F1[t] + BF[t]);
        float cc = iv * uv + f0 * C0[t] + f1 * C1[t];
        cv[t] = cc;
        hv[t] = ov * tanhf_fast(cc);
    }

    float* c_out = g_c[level & 1];
    __nv_bfloat16* h_out = g_h[level & 1];
    *(float4*)(c_out + (size_t)r * HH + j) = make_float4(cv[0], cv[1], cv[2], cv[3]);
    __nv_bfloat162 hp0 = __floats2bfloat162_rn(hv[0], hv[1]);
    __nv_bfloat162 hp1 = __floats2bfloat162_rn(hv[2], hv[3]);
    uint2 hu;
    hu.x = *reinterpret_cast<uint32_t*>(&hp0);
    hu.y = *reinterpret_cast<uint32_t*>(&hp1);
    *(uint2*)(h_out + (size_t)r * HH + j) = hu;
}

// ---------------- actor head + softmax ---------------------------------------
__global__ void final_kernel(const float* __restrict__ actor_w,
                             const float* __restrict__ actor_b,
                             const float* __restrict__ vmask,
                             float* __restrict__ out)
{
    int b = blockIdx.x;
    int lane = threadIdx.x;
    const __nv_bfloat16* hr = g_h[0] + (size_t)b * HH;   // level-0 output, row b

    float lg[NOPS];
    #pragma unroll
    for (int o = 0; o < NOPS; ++o) {
        float s = 0.f;
        for (int hh = lane; hh < HH; hh += 32)
            s += __bfloat162float(hr[hh]) * actor_w[o * HH + hh];
        #pragma unroll
        for (int off = 16; off; off >>= 1) s += __shfl_xor_sync(0xffffffffu, s, off);
        float mk = vmask[b * NOPS + o];
        lg[o] = logf(mk) + s * mk + actor_b[o] * mk;
    }
    if (lane == 0) {
        float mx = -1e30f;
        #pragma unroll
        for (int o = 0; o < NOPS; ++o) {
            lg[o] = lg[o] / 3.0f;           // TEMP
            if (lg[o] > mx) mx = lg[o];
        }
        float ev[NOPS], sum = 0.f;
        #pragma unroll
        for (int o = 0; o < NOPS; ++o) { ev[o] = expf(lg[o] - mx); sum += ev[o]; }
        float inv = 1.0f / sum;
        #pragma unroll
        for (int o = 0; o < NOPS; ++o) out[b * NOPS + o] = ev[o] * inv;
    }
}

// ---------------- launch ------------------------------------------------------
extern "C" void kernel_launch(void* const* d_in, const int* in_sizes, int n_in,
                              void* d_out, int out_size)
{
    const float* arg_hot = (const float*)d_in[0];
    const float* Wiou    = (const float*)d_in[1];
    const float* biou    = (const float*)d_in[2];
    const float* Uiou    = (const float*)d_in[3];
    const float* Wf      = (const float*)d_in[4];
    const float* bfv     = (const float*)d_in[5];
    const float* Uf      = (const float*)d_in[6];
    const float* actor_w = (const float*)d_in[7];
    const float* actor_b = (const float*)d_in[8];
    const float* vmask   = (const float*)d_in[9];
    float* out = (float*)d_out;

    prep_kernel<<<(NN * KK + 255) / 256, 256>>>(Wiou, Uiou, Wf, Uf);

    for (int l = DD - 1; l >= 0; --l) {
        int R = BB << l;
        int leaf = (l == DD - 1) ? 1 : 0;
        dim3 grid((R + 127) / 128, NN / 128);
        gemm_kernel<<<grid, 256>>>(arg_hot, l, leaf);
        int total = R * (HH / 4);
        gates_kernel<<<(total + 255) / 256, 256>>>(biou, bfv, l, leaf);
    }

    final_kernel<<<BB, 32>>>(actor_w, actor_b, vmask, out);
}

// round 4
// speedup vs baseline: 3.1170x; 3.1170x over previous
#include <cuda_runtime.h>
#include <cuda_bf16.h>
#include <cstdint>

#define BB   64          // batch
#define DD   12          // tree depth
#define VV   128         // vocab/input dim
#define HH   256         // hidden
#define NOPS 20
#define NN   1280        // 5 gates x 256
#define KK   640         // V + 2H
#define RMAX 131072      // BB << (DD-1)
#define KCH  64          // K chunk (bf16 elems) = 128 bytes/row
#define NCH  (KK / KCH)  // 10 chunks

// ---------------- static device scratch ---------------------------------------
__device__ __nv_bfloat16 g_Wp[NN * KK];                   // packed weights [p][k]
__device__ __nv_bfloat16 g_x[(size_t)BB * 4095 * VV];     // bf16 arg_hot
__device__ __nv_bfloat16 g_h[2][(size_t)RMAX * HH];       // ping-pong h (bf16)
__device__ float         g_c[2][(size_t)RMAX * HH];       // ping-pong c (fp32)

// ---------------- x conversion (fp32 -> bf16) ---------------------------------
__global__ void conv_x_kernel(const float* __restrict__ arg_hot)
{
    size_t i = ((size_t)blockIdx.x * 256 + threadIdx.x) * 4;
    float4 v = *(const float4*)(arg_hot + i);
    __nv_bfloat162 p0 = __floats2bfloat162_rn(v.x, v.y);
    __nv_bfloat162 p1 = __floats2bfloat162_rn(v.z, v.w);
    uint2 u;
    u.x = *reinterpret_cast<uint32_t*>(&p0);
    u.y = *reinterpret_cast<uint32_t*>(&p1);
    *(uint2*)(g_x + i) = u;
}

// ---------------- weight repack -----------------------------------------------
// packed col p: t = p/160 (h-block of 32), w = p%160, g = w/32 (gate), hl = w%32
//   hh = t*32+hl ; original n: i->hh, o->256+hh, u->512+hh, f0->768+hh, f1->1024+hh
// k layout: [0,128) x -> Wiou/Wf ; [128,384) child0 -> Uiou[0],Uf[*][0] ;
//           [384,640) child1 -> Uiou[1],Uf[*][1]
__global__ void prep_kernel(const float* __restrict__ Wiou,
                            const float* __restrict__ Uiou,
                            const float* __restrict__ Wf,
                            const float* __restrict__ Uf)
{
    int idx = blockIdx.x * blockDim.x + threadIdx.x;
    if (idx >= NN * KK) return;
    int p = idx / KK;
    int k = idx % KK;
    int t = p / 160, w = p % 160, g = w / 32, hl = w % 32;
    int hh = t * 32 + hl;
    int n = (g == 0) ? hh : (g == 1) ? 256 + hh : (g == 2) ? 512 + hh
          : (g == 3) ? 768 + hh : 1024 + hh;
    float v;
    if (k < VV) {
        if (n < 768)       v = Wiou[k * 768 + n];
        else if (n < 1024) v = Wf[k * HH + (n - 768)];
        else               v = Wf[k * HH + (n - 1024)];
    } else {
        int j  = (k - VV) >> 8;
        int kh = (k - VV) & 255;
        if (n < 768)       v = Uiou[(j * HH + kh) * 768 + n];
        else if (n < 1024) v = Uf[((0 * 2 + j) * HH + kh) * HH + (n - 768)];
        else               v = Uf[((1 * 2 + j) * HH + kh) * HH + (n - 1024)];
    }
    g_Wp[(size_t)p * KK + k] = __float2bfloat16(v);
}

// ---------------- activations -------------------------------------------------
__device__ __forceinline__ float sigf(float x) {
    return __fdividef(1.0f, 1.0f + __expf(-x));
}
__device__ __forceinline__ float tanh_fast(float x) {
    return __fdividef(2.0f, 1.0f + __expf(-2.0f * x)) - 1.0f;
}

// ---------------- fused GEMM + gates ------------------------------------------
// Block: 128 rows x 160 cols (5 gates x 32 h), full K=640.
// 8 warps, warp tile 16 rows x 160 cols -> each thread holds all 5 gates for
// its (row, h) elements -> gate math fully in registers, no G scratch.
__global__ __launch_bounds__(256) void fused_kernel(const float* __restrict__ biou,
                                                    const float* __restrict__ bfv,
                                                    int level, int leaf)
{
    extern __shared__ __align__(16) char dsm[];
    __shared__ float sb[1024];          // biou(768) + bf(256)

    const int m = 1 << level;
    const int R = BB * m;
    const __nv_bfloat16* __restrict__ h_prev = g_h[(level + 1) & 1];
    const float*         __restrict__ c_prev = g_c[(level + 1) & 1];
    float*               __restrict__ c_out  = g_c[level & 1];
    __nv_bfloat16*       __restrict__ h_out  = g_h[level & 1];

    const int tid  = threadIdx.x;
    const int lane = tid & 31;
    const int warp = tid >> 5;
    const int M0   = blockIdx.x * 128;
    const int nt   = blockIdx.y;        // h-block 0..7

    for (int i = tid; i < 768; i += 256) sb[i] = biou[i];
    for (int i = tid; i < 256; i += 256) sb[768 + i] = bfv[i];

    const uint32_t smem0 = (uint32_t)__cvta_generic_to_shared(dsm);
    const uint32_t asz = 128 * KCH * 2;         // 16 KB per A buffer
    const uint32_t bsz = 160 * KCH * 2;         // 20 KB per B buffer

    const int lrow = tid >> 3;   // 0..31
    const int lch  = tid & 7;    // 16B chunk within 128B row

    auto issue = [&](int K0, int buf) {
        const int kg = K0 + lch * 8;
        uint32_t abase = smem0 + buf * asz;
        #pragma unroll
        for (int it = 0; it < 4; ++it) {
            int row = lrow + it * 32;
            int r   = M0 + row;
            const __nv_bfloat16* src = g_x;   // dummy valid addr for zfill
            int sz = 0;
            if (r < R) {
                int bb   = r >> level;
                int node = r & (m - 1);
                if (kg < VV) {
                    src = g_x + ((size_t)bb * 4095 + (m - 1) + node) * VV + kg;
                    sz  = 16;
                } else if (!leaf) {
                    int j  = (kg - VV) >> 8;
                    int kh = (kg - VV) & 255;
                    src = h_prev + ((size_t)bb * (m << 1) + (node << 1) + j) * HH + kh;
                    sz  = 16;
                }
            }
            uint32_t dst = abase + row * 128 + ((lch ^ (row & 7)) << 4);
            asm volatile("cp.async.cg.shared.global [%0], [%1], 16, %2;\n"
                         :: "r"(dst), "l"(src), "r"(sz));
        }
        uint32_t bbase = smem0 + 2 * asz + buf * bsz;
        #pragma unroll
        for (int it = 0; it < 5; ++it) {
            int nrow = lrow + it * 32;
            const __nv_bfloat16* src = g_Wp + (size_t)(nt * 160 + nrow) * KK + kg;
            uint32_t dst = bbase + nrow * 128 + ((lch ^ (nrow & 7)) << 4);
            asm volatile("cp.async.cg.shared.global [%0], [%1], 16, 16;\n"
                         :: "r"(dst), "l"(src));
        }
        asm volatile("cp.async.commit_group;\n");
    };

    float acc[20][4];
    #pragma unroll
    for (int i = 0; i < 20; ++i)
        acc[i][0] = acc[i][1] = acc[i][2] = acc[i][3] = 0.f;

    issue(0, 0);
    issue(KCH, 1);

    for (int kc = 0; kc < NCH; ++kc) {
        asm volatile("cp.async.wait_group 1;\n");
        __syncthreads();
        uint32_t abase = smem0 + (kc & 1) * asz;
        uint32_t bbase = smem0 + 2 * asz + (kc & 1) * bsz;
        #pragma unroll
        for (int ks = 0; ks < KCH; ks += 16) {
            uint32_t a0, a1, a2, a3;
            {
                int arow = warp * 16 + ((lane >> 3) & 1) * 8 + (lane & 7);
                int ach  = (ks >> 3) + (lane >> 4);
                uint32_t aaddr = abase + arow * 128 + ((ach ^ (arow & 7)) << 4);
                asm volatile("ldmatrix.sync.aligned.m8n8.x4.shared.b16 {%0,%1,%2,%3}, [%4];\n"
                             : "=r"(a0), "=r"(a1), "=r"(a2), "=r"(a3) : "r"(aaddr));
            }
            #pragma unroll
            for (int p = 0; p < 10; ++p) {
                uint32_t b0, b1, b2, b3;
                int brow = p * 16 + ((lane >> 4) & 1) * 8 + (lane & 7);
                int bch  = (ks >> 3) + ((lane >> 3) & 1);
                uint32_t baddr = bbase + brow * 128 + ((bch ^ (brow & 7)) << 4);
                asm volatile("ldmatrix.sync.aligned.m8n8.x4.shared.b16 {%0,%1,%2,%3}, [%4];\n"
                             : "=r"(b0), "=r"(b1), "=r"(b2), "=r"(b3) : "r"(baddr));
                asm volatile(
                    "mma.sync.aligned.m16n8k16.row.col.f32.bf16.bf16.f32 "
                    "{%0,%1,%2,%3}, {%4,%5,%6,%7}, {%8,%9}, {%0,%1,%2,%3};\n"
                    : "+f"(acc[2 * p][0]), "+f"(acc[2 * p][1]),
                      "+f"(acc[2 * p][2]), "+f"(acc[2 * p][3])
                    : "r"(a0), "r"(a1), "r"(a2), "r"(a3), "r"(b0), "r"(b1));
                asm volatile(
                    "mma.sync.aligned.m16n8k16.row.col.f32.bf16.bf16.f32 "
                    "{%0,%1,%2,%3}, {%4,%5,%6,%7}, {%8,%9}, {%0,%1,%2,%3};\n"
                    : "+f"(acc[2 * p + 1][0]), "+f"(acc[2 * p + 1][1]),
                      "+f"(acc[2 * p + 1][2]), "+f"(acc[2 * p + 1][3])
                    : "r"(a0), "r"(a1), "r"(a2), "r"(a3), "r"(b2), "r"(b3));
            }
        }
        __syncthreads();
        if (kc + 2 < NCH) issue((kc + 2) * KCH, (kc & 1));
        else              asm volatile("cp.async.commit_group;\n");
    }

    // ---- fused gate epilogue (registers -> c fp32 + h bf16) ----
    // acc flat index nf_flat = g*4 + nf ; cols = nf_flat*8 + (lane&3)*2 + {0,1}
    const int r0 = M0 + warp * 16 + (lane >> 2);
    const int hb = nt * 32;
    #pragma unroll
    for (int nf = 0; nf < 4; ++nf) {
        int hh = hb + nf * 8 + ((lane & 3) << 1);
        float bI0 = sb[hh],       bI1 = sb[hh + 1];
        float bO0 = sb[256 + hh], bO1 = sb[257 + hh];
        float bU0 = sb[512 + hh], bU1 = sb[513 + hh];
        float bF0 = sb[768 + hh], bF1 = sb[769 + hh];
        #pragma unroll
        for (int e = 0; e < 2; ++e) {
            int r = r0 + e * 8;
            if (r >= R) continue;
            float c00 = 0.f, c01 = 0.f, c10 = 0.f, c11 = 0.f;
            if (!leaf) {
                int bb = r >> level, node = r & (m - 1);
                size_t chb = ((size_t)bb * (m << 1) + (node << 1)) * HH + hh;
                float2 v0 = *(const float2*)(c_prev + chb);
                float2 v1 = *(const float2*)(c_prev + chb + HH);
                c00 = v0.x; c01 = v0.y; c10 = v1.x; c11 = v1.y;
            }
            float iA  = sigf(acc[nf][e * 2 + 0] + bI0);
            float iB  = sigf(acc[nf][e * 2 + 1] + bI1);
            float oA  = sigf(acc[4 + nf][e * 2 + 0] + bO0);
            float oB  = sigf(acc[4 + nf][e * 2 + 1] + bO1);
            float uA  = tanh_fast(acc[8 + nf][e * 2 + 0] + bU0);
            float uB  = tanh_fast(acc[8 + nf][e * 2 + 1] + bU1);
            float f0A = sigf(acc[12 + nf][e * 2 + 0] + bF0);
            float f0B = sigf(acc[12 + nf][e * 2 + 1] + bF1);
            float f1A = sigf(acc[16 + nf][e * 2 + 0] + bF0);
            float f1B = sigf(acc[16 + nf][e * 2 + 1] + bF1);
            float cA = iA * uA + f0A * c00 + f1A * c10;
            float cB = iB * uB + f0B * c01 + f1B * c11;
            float hA = oA * tanh_fast(cA);
            float hB = oB * tanh_fast(cB);
            *(float2*)(c_out + (size_t)r * HH + hh) = make_float2(cA, cB);
            __nv_bfloat162 hp = __floats2bfloat162_rn(hA, hB);
            *(uint32_t*)(h_out + (size_t)r * HH + hh) = *reinterpret_cast<uint32_t*>(&hp);
        }
    }
}

// ---------------- actor head + softmax ---------------------------------------
__global__ void final_kernel(const float* __restrict__ actor_w,
                             const float* __restrict__ actor_b,
                             const float* __restrict__ vmask,
                             float* __restrict__ out)
{
    int b = blockIdx.x;
    int lane = threadIdx.x;
    const __nv_bfloat16* hr = g_h[0] + (size_t)b * HH;   // level-0 output, row b

    float lg[NOPS];
    #pragma unroll
    for (int o = 0; o < NOPS; ++o) {
        float s = 0.f;
        for (int hh = lane; hh < HH; hh += 32)
            s += __bfloat162float(hr[hh]) * actor_w[o * HH + hh];
        #pragma unroll
        for (int off = 16; off; off >>= 1) s += __shfl_xor_sync(0xffffffffu, s, off);
        float mk = vmask[b * NOPS + o];
        lg[o] = logf(mk) + s * mk + actor_b[o] * mk;
    }
    if (lane == 0) {
        float mx = -1e30f;
        #pragma unroll
        for (int o = 0; o < NOPS; ++o) {
            lg[o] = lg[o] / 3.0f;           // TEMP
            if (lg[o] > mx) mx = lg[o];
        }
        float ev[NOPS], sum = 0.f;
        #pragma unroll
        for (int o = 0; o < NOPS; ++o) { ev[o] = expf(lg[o] - mx); sum += ev[o]; }
        float inv = 1.0f / sum;
        #pragma unroll
        for (int o = 0; o < NOPS; ++o) out[b * NOPS + o] = ev[o] * inv;
    }
}

// ---------------- launch ------------------------------------------------------
extern "C" void kernel_launch(void* const* d_in, const int* in_sizes, int n_in,
                              void* d_out, int out_size)
{
    const float* arg_hot = (const float*)d_in[0];
    const float* Wiou    = (const float*)d_in[1];
    const float* biou    = (const float*)d_in[2];
    const float* Uiou    = (const float*)d_in[3];
    const float* Wf      = (const float*)d_in[4];
    const float* bfv     = (const float*)d_in[5];
    const float* Uf      = (const float*)d_in[6];
    const float* actor_w = (const float*)d_in[7];
    const float* actor_b = (const float*)d_in[8];
    const float* vmask   = (const float*)d_in[9];
    float* out = (float*)d_out;

    cudaFuncSetAttribute(fused_kernel,
                         cudaFuncAttributeMaxDynamicSharedMemorySize, 73728);

    // 64*4095*128 / (256*4) = 32760 exactly
    conv_x_kernel<<<32760, 256>>>(arg_hot);
    prep_kernel<<<(NN * KK + 255) / 256, 256>>>(Wiou, Uiou, Wf, Uf);

    for (int l = DD - 1; l >= 0; --l) {
        int R = BB << l;
        int leaf = (l == DD - 1) ? 1 : 0;
        dim3 grid((R + 127) / 128, 8);
        fused_kernel<<<grid, 256, 73728>>>(biou, bfv, l, leaf);
    }

    final_kernel<<<BB, 32>>>(actor_w, actor_b, vmask, out);
}

// round 6
// speedup vs baseline: 4.2896x; 1.3762x over previous
#include <cuda_runtime.h>
#include <cuda_bf16.h>
#include <cstdint>

#define BB   64          // batch
#define DD   12          // tree depth
#define VV   128         // vocab/input dim
#define HH   256         // hidden
#define NOPS 20
#define NN   1280        // 5 gates x 256
#define KK   640         // V + 2H
#define RMAX 131072      // BB << (DD-1)
#define KCH  64          // K chunk (bf16 elems) = 128 bytes/row
#define NT   160         // N tile per block: 2 x (5 gates x 16 h)

// ---------------- static device scratch ---------------------------------------
__device__ __nv_bfloat16 g_Wp[NN * KK];                   // packed weights [p][k]
__device__ __nv_bfloat16 g_x[(size_t)BB * 4095 * VV];     // bf16 arg_hot
__device__ __nv_bfloat16 g_h[2][(size_t)RMAX * HH];       // ping-pong h (bf16)
__device__ float         g_c[2][(size_t)RMAX * HH];       // ping-pong c (fp32)

// ---------------- x conversion (fp32 -> bf16) ---------------------------------
__global__ void conv_x_kernel(const float* __restrict__ arg_hot)
{
    size_t i = ((size_t)blockIdx.x * 256 + threadIdx.x) * 4;
    float4 v = *(const float4*)(arg_hot + i);
    __nv_bfloat162 p0 = __floats2bfloat162_rn(v.x, v.y);
    __nv_bfloat162 p1 = __floats2bfloat162_rn(v.z, v.w);
    uint2 u;
    u.x = *reinterpret_cast<uint32_t*>(&p0);
    u.y = *reinterpret_cast<uint32_t*>(&p1);
    *(uint2*)(g_x + i) = u;
}

// ---------------- weight repack -----------------------------------------------
// packed col p: hb16 = p/80 (h-block of 16), w = p%80, g = w/16, hl = w%16
//   hh = hb16*16+hl ; original n: i->hh, o->256+hh, u->512+hh, f0->768+hh, f1->1024+hh
// k layout: [0,128) x -> Wiou/Wf ; [128,384) child0 ; [384,640) child1
__global__ void prep_kernel(const float* __restrict__ Wiou,
                            const float* __restrict__ Uiou,
                            const float* __restrict__ Wf,
                            const float* __restrict__ Uf)
{
    int idx = blockIdx.x * blockDim.x + threadIdx.x;
    if (idx >= NN * KK) return;
    int p = idx / KK;
    int k = idx % KK;
    int hb16 = p / 80, w = p % 80, g = w / 16, hl = w % 16;
    int hh = hb16 * 16 + hl;
    int n = (g == 0) ? hh : (g == 1) ? 256 + hh : (g == 2) ? 512 + hh
          : (g == 3) ? 768 + hh : 1024 + hh;
    float v;
    if (k < VV) {
        if (n < 768)       v = Wiou[k * 768 + n];
        else if (n < 1024) v = Wf[k * HH + (n - 768)];
        else               v = Wf[k * HH + (n - 1024)];
    } else {
        int j  = (k - VV) >> 8;
        int kh = (k - VV) & 255;
        if (n < 768)       v = Uiou[(j * HH + kh) * 768 + n];
        else if (n < 1024) v = Uf[((0 * 2 + j) * HH + kh) * HH + (n - 768)];
        else               v = Uf[((1 * 2 + j) * HH + kh) * HH + (n - 1024)];
    }
    g_Wp[(size_t)p * KK + k] = __float2bfloat16(v);
}

// ---------------- activations -------------------------------------------------
__device__ __forceinline__ float sigf(float x) {
    return __fdividef(1.0f, 1.0f + __expf(-x));
}
__device__ __forceinline__ float tanh_fast(float x) {
    return __fdividef(2.0f, 1.0f + __expf(-2.0f * x)) - 1.0f;
}

// ---------------- fused GEMM + gates ------------------------------------------
// Block: 128 rows x 160 cols; 8 warps as 4(M) x 2(N): warp tile 32 x 80
//   -> per 16-K step: 2 A + 5 B ldmatrix.x4 (vs 11 with 16x160 tiling).
// Each warp-half's 80 cols = 5 gates x 16 h -> gate math fully in registers.
// nch = 2 at leaf level (h_child = 0 => K in [128,640) contributes nothing).
__global__ __launch_bounds__(256, 2) void fused_kernel(const float* __restrict__ biou,
                                                       const float* __restrict__ bfv,
                                                       int level, int leaf, int nch)
{
    extern __shared__ __align__(16) char dsm[];
    __shared__ float sb[1024];          // biou(768) + bf(256)

    const int m = 1 << level;
    const int R = BB * m;
    const __nv_bfloat16* __restrict__ h_prev = g_h[(level + 1) & 1];
    const float*         __restrict__ c_prev = g_c[(level + 1) & 1];
    float*               __restrict__ c_out  = g_c[level & 1];
    __nv_bfloat16*       __restrict__ h_out  = g_h[level & 1];

    const int tid  = threadIdx.x;
    const int lane = tid & 31;
    const int warp = tid >> 5;
    const int wm   = warp & 3;          // 4 warps in M (32 rows each)
    const int wn   = warp >> 2;         // 2 warps in N (80 cols each)
    const int M0   = blockIdx.x * 128;
    const int nt   = blockIdx.y;        // h-block of 32 (0..7)

    for (int i = tid; i < 768; i += 256) sb[i] = biou[i];
    for (int i = tid; i < 256; i += 256) sb[768 + i] = bfv[i];

    const uint32_t smem0 = (uint32_t)__cvta_generic_to_shared(dsm);
    const uint32_t asz = 128 * 128;     // 16 KB per A buffer
    const uint32_t bsz = NT * 128;      // 20 KB per B buffer

    const int lrow = tid >> 3;   // 0..31
    const int lch  = tid & 7;    // 16B chunk within 128B row

    auto issue = [&](int K0, int buf) {
        const int kg = K0 + lch * 8;
        uint32_t abase = smem0 + buf * asz;
        #pragma unroll
        for (int it = 0; it < 4; ++it) {
            int row = lrow + it * 32;
            int r   = M0 + row;
            const __nv_bfloat16* src = g_x;   // dummy valid addr for zfill
            int sz = 0;
            if (r < R) {
                int bb   = r >> level;
                int node = r & (m - 1);
                if (kg < VV) {
                    src = g_x + ((size_t)bb * 4095 + (m - 1) + node) * VV + kg;
                    sz  = 16;
                } else if (!leaf) {
                    int j  = (kg - VV) >> 8;
                    int kh = (kg - VV) & 255;
                    src = h_prev + ((size_t)bb * (m << 1) + (node << 1) + j) * HH + kh;
                    sz  = 16;
                }
            }
            uint32_t dst = abase + row * 128 + ((lch ^ (row & 7)) << 4);
            asm volatile("cp.async.cg.shared.global [%0], [%1], 16, %2;\n"
                         :: "r"(dst), "l"(src), "r"(sz));
        }
        uint32_t bbase = smem0 + 2 * asz + buf * bsz;
        #pragma unroll
        for (int it = 0; it < 5; ++it) {
            int nrow = lrow + it * 32;
            const __nv_bfloat16* src = g_Wp + (size_t)(nt * NT + nrow) * KK + kg;
            uint32_t dst = bbase + nrow * 128 + ((lch ^ (nrow & 7)) << 4);
            asm volatile("cp.async.cg.shared.global [%0], [%1], 16, 16;\n"
                         :: "r"(dst), "l"(src));
        }
        asm volatile("cp.async.commit_group;\n");
    };

    float acc[2][10][4];
    #pragma unroll
    for (int a = 0; a < 2; ++a)
        #pragma unroll
        for (int c = 0; c < 10; ++c)
            #pragma unroll
            for (int d = 0; d < 4; ++d) acc[a][c][d] = 0.f;

    issue(0, 0);
    issue(KCH, 1);

    for (int kc = 0; kc < nch; ++kc) {
        asm volatile("cp.async.wait_group 1;\n");
        __syncthreads();
        uint32_t abase = smem0 + (kc & 1) * asz;
        uint32_t bbase = smem0 + 2 * asz + (kc & 1) * bsz;
        #pragma unroll
        for (int ks = 0; ks < KCH; ks += 16) {
            uint32_t af[2][4];
            #pragma unroll
            for (int mi = 0; mi < 2; ++mi) {
                int arow = wm * 32 + mi * 16 + ((lane >> 3) & 1) * 8 + (lane & 7);
                int ach  = (ks >> 3) + (lane >> 4);
                uint32_t aaddr = abase + arow * 128 + ((ach ^ (arow & 7)) << 4);
                asm volatile("ldmatrix.sync.aligned.m8n8.x4.shared.b16 {%0,%1,%2,%3}, [%4];\n"
                             : "=r"(af[mi][0]), "=r"(af[mi][1]),
                               "=r"(af[mi][2]), "=r"(af[mi][3]) : "r"(aaddr));
            }
            #pragma unroll
            for (int p5 = 0; p5 < 5; ++p5) {
                uint32_t b0, b1, b2, b3;
                int brow = wn * 80 + p5 * 16 + ((lane >> 4) & 1) * 8 + (lane & 7);
                int bch  = (ks >> 3) + ((lane >> 3) & 1);
                uint32_t baddr = bbase + brow * 128 + ((bch ^ (brow & 7)) << 4);
                asm volatile("ldmatrix.sync.aligned.m8n8.x4.shared.b16 {%0,%1,%2,%3}, [%4];\n"
                             : "=r"(b0), "=r"(b1), "=r"(b2), "=r"(b3) : "r"(baddr));
                #pragma unroll
                for (int mi = 0; mi < 2; ++mi) {
                    asm volatile(
                        "mma.sync.aligned.m16n8k16.row.col.f32.bf16.bf16.f32 "
                        "{%0,%1,%2,%3}, {%4,%5,%6,%7}, {%8,%9}, {%0,%1,%2,%3};\n"
                        : "+f"(acc[mi][2 * p5][0]), "+f"(acc[mi][2 * p5][1]),
                          "+f"(acc[mi][2 * p5][2]), "+f"(acc[mi][2 * p5][3])
                        : "r"(af[mi][0]), "r"(af[mi][1]), "r"(af[mi][2]), "r"(af[mi][3]),
                          "r"(b0), "r"(b1));
                    asm volatile(
                        "mma.sync.aligned.m16n8k16.row.col.f32.bf16.bf16.f32 "
                        "{%0,%1,%2,%3}, {%4,%5,%6,%7}, {%8,%9}, {%0,%1,%2,%3};\n"
                        : "+f"(acc[mi][2 * p5 + 1][0]), "+f"(acc[mi][2 * p5 + 1][1]),
                          "+f"(acc[mi][2 * p5 + 1][2]), "+f"(acc[mi][2 * p5 + 1][3])
                        : "r"(af[mi][0]), "r"(af[mi][1]), "r"(af[mi][2]), "r"(af[mi][3]),
                          "r"(b2), "r"(b3));
                }
            }
        }
        __syncthreads();
        if (kc + 2 < nch) issue((kc + 2) * KCH, (kc & 1));
        else              asm volatile("cp.async.commit_group;\n");
    }

    // ---- fused gate epilogue ----
    // thread owns rows r0+16*mi+8*e, h pairs at hbase + 8*u (+0,+1);
    // gate g lives in acc[mi][2g+u][2e+pair]
    const int r0    = M0 + wm * 32 + (lane >> 2);
    const int hbase = nt * 32 + wn * 16 + ((lane & 3) << 1);
    #pragma unroll
    for (int mi = 0; mi < 2; ++mi) {
        #pragma unroll
        for (int e = 0; e < 2; ++e) {
            int r = r0 + mi * 16 + e * 8;
            if (r >= R) continue;
            float cp0[2][2], cp1[2][2];     // [u][pair]
            if (!leaf) {
                int bb = r >> level, node = r & (m - 1);
                size_t chb = ((size_t)bb * (m << 1) + (node << 1)) * HH;
                #pragma unroll
                for (int u = 0; u < 2; ++u) {
                    float2 v0 = *(const float2*)(c_prev + chb + hbase + u * 8);
                    float2 v1 = *(const float2*)(c_prev + chb + HH + hbase + u * 8);
                    cp0[u][0] = v0.x; cp0[u][1] = v0.y;
                    cp1[u][0] = v1.x; cp1[u][1] = v1.y;
                }
            } else {
                #pragma unroll
                for (int u = 0; u < 2; ++u)
                    cp0[u][0] = cp0[u][1] = cp1[u][0] = cp1[u][1] = 0.f;
            }
            #pragma unroll
            for (int u = 0; u < 2; ++u) {
                int h = hbase + u * 8;
                float cv[2], hv[2];
                #pragma unroll
                for (int q = 0; q < 2; ++q) {
                    float iv = sigf(acc[mi][0 + u][2 * e + q] + sb[h + q]);
                    float ov = sigf(acc[mi][2 + u][2 * e + q] + sb[256 + h + q]);
                    float uv = tanh_fast(acc[mi][4 + u][2 * e + q] + sb[512 + h + q]);
                    float f0 = sigf(acc[mi][6 + u][2 * e + q] + sb[768 + h + q]);
                    float f1 = sigf(acc[mi][8 + u][2 * e + q] + sb[768 + h + q]);
                    float cc = iv * uv + f0 * cp0[u][q] + f1 * cp1[u][q];
                    cv[q] = cc;
                    hv[q] = ov * tanh_fast(cc);
                }
                *(float2*)(c_out + (size_t)r * HH + h) = make_float2(cv[0], cv[1]);
                __nv_bfloat162 hp = __floats2bfloat162_rn(hv[0], hv[1]);
                *(uint32_t*)(h_out + (size_t)r * HH + h) =
                    *reinterpret_cast<uint32_t*>(&hp);
            }
        }
    }
}

// ---------------- actor head + softmax ---------------------------------------
__global__ void final_kernel(const float* __restrict__ actor_w,
                             const float* __restrict__ actor_b,
                             const float* __restrict__ vmask,
                             float* __restrict__ out)
{
    int b = blockIdx.x;
    int lane = threadIdx.x;
    const __nv_bfloat16* hr = g_h[0] + (size_t)b * HH;   // level-0 output, row b

    float lg[NOPS];
    #pragma unroll
    for (int o = 0; o < NOPS; ++o) {
        float s = 0.f;
        for (int hh = lane; hh < HH; hh += 32)
            s += __bfloat162float(hr[hh]) * actor_w[o * HH + hh];
        #pragma unroll
        for (int off = 16; off; off >>= 1) s += __shfl_xor_sync(0xffffffffu, s, off);
        float mk = vmask[b * NOPS + o];
        lg[o] = logf(mk) + s * mk + actor_b[o] * mk;
    }
    if (lane == 0) {
        float mx = -1e30f;
        #pragma unroll
        for (int o = 0; o < NOPS; ++o) {
            lg[o] = lg[o] / 3.0f;           // TEMP
            if (lg[o] > mx) mx = lg[o];
        }
        float ev[NOPS], sum = 0.f;
        #pragma unroll
        for (int o = 0; o < NOPS; ++o) { ev[o] = expf(lg[o] - mx); sum += ev[o]; }
        float inv = 1.0f / sum;
        #pragma unroll
        for (int o = 0; o < NOPS; ++o) out[b * NOPS + o] = ev[o] * inv;
    }
}

// ---------------- launch ------------------------------------------------------
extern "C" void kernel_launch(void* const* d_in, const int* in_sizes, int n_in,
                              void* d_out, int out_size)
{
    const float* arg_hot = (const float*)d_in[0];
    const float* Wiou    = (const float*)d_in[1];
    const float* biou    = (const float*)d_in[2];
    const float* Uiou    = (const float*)d_in[3];
    const float* Wf      = (const float*)d_in[4];
    const float* bfv     = (const float*)d_in[5];
    const float* Uf      = (const float*)d_in[6];
    const float* actor_w = (const float*)d_in[7];
    const float* actor_b = (const float*)d_in[8];
    const float* vmask   = (const float*)d_in[9];
    float* out = (float*)d_out;

    cudaFuncSetAttribute(fused_kernel,
                         cudaFuncAttributeMaxDynamicSharedMemorySize, 73728);

    // 64*4095*128 / (256*4) = 32760 exactly
    conv_x_kernel<<<32760, 256>>>(arg_hot);
    prep_kernel<<<(NN * KK + 255) / 256, 256>>>(Wiou, Uiou, Wf, Uf);

    for (int l = DD - 1; l >= 0; --l) {
        int R = BB << l;
        int leaf = (l == DD - 1) ? 1 : 0;
        int nch  = leaf ? 2 : 10;     // leaf: h_child = 0, only x-K contributes
        dim3 grid((R + 127) / 128, 8);
        fused_kernel<<<grid, 256, 73728>>>(biou, bfv, l, leaf, nch);
    }

    final_kernel<<<BB, 32>>>(actor_w, actor_b, vmask, out);
}